// round 8
// baseline (speedup 1.0000x reference)
#include <cuda_runtime.h>
#include <cuda_bf16.h>
#include <cstdint>

#define BATCH_TOT 524288
#define KDIM 128
#define NDIM 128
#define CHUNK_ROWS 64
#define NCHUNKS (BATCH_TOT / CHUNK_ROWS)   // 8192

// bf16 tiles, row pitch 272 bytes (17 x 16B) -> conflict-free ldmatrix
#define TPITCH 272
#define WTILE_BYTES (128 * TPITCH)         // 34816
#define XTILE_BYTES (CHUNK_ROWS * TPITCH)  // 17408

// smem layout (bytes)
#define SM_WH   0
#define SM_WL   (SM_WH + WTILE_BYTES)
#define SM_XH   (SM_WL + WTILE_BYTES)
#define SM_XL   (SM_XH + XTILE_BYTES)
#define SM_QUAD (SM_XL + XTILE_BYTES)      // 64 f32
#define SM_SPB  (SM_QUAD + 256)            // 128 f32
#define SM_SPW  (SM_SPB + 512)             // 128 f32
#define SM_TOTAL (SM_SPW + 512)            // 105,728 B -> 2 CTAs/SM

// global scratch written by prep kernel
__device__ __align__(16) unsigned char g_whi[WTILE_BYTES];
__device__ __align__(16) unsigned char g_wlo[WTILE_BYTES];
__device__ float g_spw[128];
__device__ float g_spb[128];

__device__ __forceinline__ uint32_t smem_u32(const void* p) {
    uint32_t a;
    asm("{ .reg .u64 t; cvta.to.shared.u64 t, %1; cvt.u32.u64 %0, t; }" : "=r"(a) : "l"(p));
    return a;
}
__device__ __forceinline__ void ldsm_x4(uint32_t& r0, uint32_t& r1, uint32_t& r2, uint32_t& r3,
                                        uint32_t addr) {
    asm volatile("ldmatrix.sync.aligned.m8n8.x4.shared.b16 {%0,%1,%2,%3}, [%4];"
                 : "=r"(r0), "=r"(r1), "=r"(r2), "=r"(r3) : "r"(addr));
}
__device__ __forceinline__ void mma_bf16(float* c, const uint32_t* a, uint32_t b0, uint32_t b1) {
    asm volatile(
        "mma.sync.aligned.m16n8k16.row.col.f32.bf16.bf16.f32 "
        "{%0,%1,%2,%3}, {%4,%5,%6,%7}, {%8,%9}, {%0,%1,%2,%3};"
        : "+f"(c[0]), "+f"(c[1]), "+f"(c[2]), "+f"(c[3])
        : "r"(a[0]), "r"(a[1]), "r"(a[2]), "r"(a[3]), "r"(b0), "r"(b1));
}

// ---------- prep: split W -> bf16 hi/lo [n][k] pitch 272, softplus params, KL scalar ----------
__global__ __launch_bounds__(1024)
void prep_kernel(const float* __restrict__ w_mu, const float* __restrict__ w_sigma,
                 const float* __restrict__ b_sigma, float* __restrict__ out_kl)
{
    __shared__ float red[1024];
    const int tid = threadIdx.x;
    float s = 0.f;
    #pragma unroll
    for (int i = 0; i < 16; i++) {
        int idx = tid + i * 1024;            // idx = k*128 + n
        float w = w_mu[idx];
        s += fabsf(w);
        int k = idx >> 7, n = idx & 127;
        __nv_bfloat16 hi = __float2bfloat16(w);
        __nv_bfloat16 lo = __float2bfloat16(w - __bfloat162float(hi));
        int off = n * TPITCH + k * 2;        // B[n][k] = W[k][n]
        *(__nv_bfloat16*)(g_whi + off) = hi;
        *(__nv_bfloat16*)(g_wlo + off) = lo;
    }
    float t = 0.f;
    if (tid < 128) {
        float spw = log1pf(expf(w_sigma[tid]));
        g_spw[tid] = spw;
        t = logf(spw) - spw;                 // 128 * mean_j == sum_j
        g_spb[tid] = log1pf(expf(b_sigma[tid]));
    }
    red[tid] = t - s;
    __syncthreads();
    for (int o = 512; o > 0; o >>= 1) {
        if (tid < o) red[tid] += red[tid + o];
        __syncthreads();
    }
    if (tid == 0) out_kl[0] = -0.5f * red[0];
}

// ---------- fused persistent kernel: 256 threads, 2 CTAs/SM, 64-row chunks, 8 warps 2x4 ----------
__global__ __launch_bounds__(256, 2)
void fused_kernel(const float* __restrict__ x, const float* __restrict__ b_mu,
                  float* __restrict__ out)
{
    extern __shared__ __align__(16) unsigned char smem[];
    const uint32_t sbase = smem_u32(smem);
    const int tid = threadIdx.x, wid = tid >> 5, lane = tid & 31;

    // ---- one-time: W tiles global->smem, params ----
    {
        const float4* sh = (const float4*)g_whi;
        const float4* sl = (const float4*)g_wlo;
        float4* dh = (float4*)(smem + SM_WH);
        float4* dl = (float4*)(smem + SM_WL);
        #pragma unroll
        for (int i = 0; i < 8; i++) {        // 8*256 = 2048
            int idx = tid + i * 256;
            dh[idx] = sh[idx];
            dl[idx] = sl[idx];
        }
        if (tid < 128) {                     // tail to 2176
            int idx = 2048 + tid;
            dh[idx] = sh[idx];
            dl[idx] = sl[idx];
        }
    }
    if (tid < 128) {
        ((float*)(smem + SM_SPW))[tid] = g_spw[tid];
        ((float*)(smem + SM_SPB))[tid] = g_spb[tid];
    }

    // warp tile: 32 rows x 32 cols; warps in 2 (m) x 4 (n) grid
    const int m0 = (wid >> 2) * 32;
    const int n0 = (wid & 3) * 32;
    const int g = lane >> 2, tig = lane & 3;

    // b_mu fragment: cols n0 + ni*16 + h*8 + 2*tig
    float2 bm[2][2];
    #pragma unroll
    for (int ni = 0; ni < 2; ni++)
        #pragma unroll
        for (int h = 0; h < 2; h++)
            bm[ni][h] = __ldg((const float2*)(b_mu + n0 + ni * 16 + h * 8 + 2 * tig));

    // ldmatrix lane addresses
    const uint32_t a_lane = sbase + (uint32_t)((m0 + (lane & 15)) * TPITCH + (lane >> 4) * 16);
    const uint32_t b_lane = sbase + (uint32_t)((n0 + (lane >> 4) * 8 + (lane & 7)) * TPITCH +
                                               ((lane >> 3) & 1) * 16);
    const int row = tid >> 2, quarter = tid & 3;  // convert: 4 threads per row, 32 floats each

    __syncthreads();

    for (int chunk = blockIdx.x; chunk < NCHUNKS; chunk += gridDim.x) {
        const size_t rowBase = (size_t)chunk * CHUNK_ROWS;

        // ---- convert x -> xh/xl bf16 tiles + per-row quad ----
        {
            const float4* xr = (const float4*)(x + (rowBase + row) * KDIM + quarter * 32);
            const float* spw = (const float*)(smem + SM_SPW) + quarter * 32;
            unsigned char* xh = smem + SM_XH + row * TPITCH + quarter * 64;
            unsigned char* xl = smem + SM_XL + row * TPITCH + quarter * 64;
            float q = 0.f;
            #pragma unroll
            for (int i = 0; i < 8; i++) {
                float4 v = xr[i];
                q = fmaf(v.x * v.x, spw[4 * i + 0], q);
                q = fmaf(v.y * v.y, spw[4 * i + 1], q);
                q = fmaf(v.z * v.z, spw[4 * i + 2], q);
                q = fmaf(v.w * v.w, spw[4 * i + 3], q);
                __nv_bfloat16 h0 = __float2bfloat16(v.x), h1 = __float2bfloat16(v.y);
                __nv_bfloat16 h2 = __float2bfloat16(v.z), h3 = __float2bfloat16(v.w);
                __nv_bfloat16 l0 = __float2bfloat16(v.x - __bfloat162float(h0));
                __nv_bfloat16 l1 = __float2bfloat16(v.y - __bfloat162float(h1));
                __nv_bfloat16 l2 = __float2bfloat16(v.z - __bfloat162float(h2));
                __nv_bfloat16 l3 = __float2bfloat16(v.w - __bfloat162float(h3));
                uint32_t uh0 = ((uint32_t)__bfloat16_as_ushort(h1) << 16) | __bfloat16_as_ushort(h0);
                uint32_t uh1 = ((uint32_t)__bfloat16_as_ushort(h3) << 16) | __bfloat16_as_ushort(h2);
                uint32_t ul0 = ((uint32_t)__bfloat16_as_ushort(l1) << 16) | __bfloat16_as_ushort(l0);
                uint32_t ul1 = ((uint32_t)__bfloat16_as_ushort(l3) << 16) | __bfloat16_as_ushort(l2);
                *(uint2*)(xh + i * 8) = make_uint2(uh0, uh1);
                *(uint2*)(xl + i * 8) = make_uint2(ul0, ul1);
            }
            q += __shfl_xor_sync(0xffffffffu, q, 1);
            q += __shfl_xor_sync(0xffffffffu, q, 2);
            if (quarter == 0) ((float*)(smem + SM_QUAD))[row] = q;
        }
        __syncthreads();

        // ---- GEMM: fused 3-term bf16 split, 32x32 warp tile ----
        float acc[2][2][2][4];                 // [mi][ni][h][4]
        #pragma unroll
        for (int mi = 0; mi < 2; mi++)
            #pragma unroll
            for (int ni = 0; ni < 2; ni++)
                #pragma unroll
                for (int h = 0; h < 2; h++)
                    #pragma unroll
                    for (int j = 0; j < 4; j++) acc[mi][ni][h][j] = 0.f;

        #pragma unroll
        for (int kc = 0; kc < 8; kc++) {
            const uint32_t ko = kc * 32;
            uint32_t ah[2][4], al[2][4], bh[2][4], bl[2][4];
            #pragma unroll
            for (int mi = 0; mi < 2; mi++) {
                ldsm_x4(ah[mi][0], ah[mi][1], ah[mi][2], ah[mi][3],
                        a_lane + SM_XH + mi * (16 * TPITCH) + ko);
                ldsm_x4(al[mi][0], al[mi][1], al[mi][2], al[mi][3],
                        a_lane + SM_XL + mi * (16 * TPITCH) + ko);
            }
            #pragma unroll
            for (int ni = 0; ni < 2; ni++) {
                ldsm_x4(bh[ni][0], bh[ni][1], bh[ni][2], bh[ni][3],
                        b_lane + SM_WH + ni * (16 * TPITCH) + ko);
                ldsm_x4(bl[ni][0], bl[ni][1], bl[ni][2], bl[ni][3],
                        b_lane + SM_WL + ni * (16 * TPITCH) + ko);
            }
            #pragma unroll
            for (int mi = 0; mi < 2; mi++)
                #pragma unroll
                for (int ni = 0; ni < 2; ni++) {
                    mma_bf16(acc[mi][ni][0], ah[mi], bh[ni][0], bh[ni][1]);  // xh*wh
                    mma_bf16(acc[mi][ni][1], ah[mi], bh[ni][2], bh[ni][3]);
                    mma_bf16(acc[mi][ni][0], al[mi], bh[ni][0], bh[ni][1]);  // xl*wh
                    mma_bf16(acc[mi][ni][1], al[mi], bh[ni][2], bh[ni][3]);
                    mma_bf16(acc[mi][ni][0], ah[mi], bl[ni][0], bl[ni][1]);  // xh*wl
                    mma_bf16(acc[mi][ni][1], ah[mi], bl[ni][2], bl[ni][3]);
                }
        }

        // ---- mu epilogue: fragments -> global ----
        #pragma unroll
        for (int mi = 0; mi < 2; mi++) {
            float* o0 = out + (rowBase + m0 + mi * 16 + g) * NDIM + n0;
            float* o1 = o0 + 8 * NDIM;
            #pragma unroll
            for (int ni = 0; ni < 2; ni++)
                #pragma unroll
                for (int h = 0; h < 2; h++) {
                    const float* c = acc[mi][ni][h];
                    int col = ni * 16 + h * 8 + 2 * tig;
                    float2 b = bm[ni][h];
                    *(float2*)(o0 + col) = make_float2(c[0] + b.x, c[1] + b.y);
                    *(float2*)(o1 + col) = make_float2(c[2] + b.x, c[3] + b.y);
                }
        }

        // ---- sigma epilogue: coalesced float4 ----
        {
            const float* quad = (const float*)(smem + SM_QUAD);
            const float4* spb4 = (const float4*)(smem + SM_SPB);
            float4* sg = (float4*)(out + (size_t)BATCH_TOT * NDIM + rowBase * NDIM);
            #pragma unroll
            for (int i = 0; i < 8; i++) {
                int idx = tid + i * 256;          // 0..2047 float4
                int r = idx >> 5, c4 = idx & 31;
                float q = quad[r];
                float4 s = spb4[c4];
                sg[idx] = make_float4(q + s.x, q + s.y, q + s.z, q + s.w);
            }
        }
        __syncthreads();   // xh/xl/quad reused next chunk
    }
}

extern "C" void kernel_launch(void* const* d_in, const int* in_sizes, int n_in,
                              void* d_out, int out_size)
{
    const float* x       = (const float*)d_in[0];
    const float* w_mu    = (const float*)d_in[1];
    const float* w_sigma = (const float*)d_in[2];
    const float* b_mu    = (const float*)d_in[3];
    const float* b_sigma = (const float*)d_in[4];
    float* out = (float*)d_out;

    int dev = 0, sms = 148;
    cudaGetDevice(&dev);
    cudaDeviceGetAttribute(&sms, cudaDevAttrMultiProcessorCount, dev);
    int grid = 2 * sms;
    if (grid > NCHUNKS) grid = NCHUNKS;

    cudaFuncSetAttribute(fused_kernel, cudaFuncAttributeMaxDynamicSharedMemorySize, SM_TOTAL);

    prep_kernel<<<1, 1024>>>(w_mu, w_sigma, b_sigma, out + (size_t)out_size - 1);
    fused_kernel<<<grid, 256, SM_TOTAL>>>(x, b_mu, out);
}